// round 4
// baseline (speedup 1.0000x reference)
#include <cuda_runtime.h>
#include <cstdint>

#define NPTS  16384
#define SPTS  1024
#define KNN   32
#define NCHUNK 512          // chunks per batch
#define CPTS   32           // points per chunk

typedef unsigned long long u64;

__device__ int    g_group_idx[4*SPTS*KNN];
__device__ float4 g_sxyz[4*NPTS];    // sorted points: x,y,z, bitcast(orig idx)
__device__ float4 g_cc[4*NCHUNK];    // chunk center xyz + radius (upper bound)

extern __shared__ float s_raw[];

__device__ __forceinline__ float sq3(float x, float y, float z) {
    return __fadd_rn(__fadd_rn(__fmul_rn(x, x), __fmul_rn(y, y)), __fmul_rn(z, z));
}
__device__ __forceinline__ u64 pk(float a, float b) {
    u64 r; asm("mov.b64 %0,{%1,%2};" : "=l"(r) : "f"(a), "f"(b)); return r;
}
__device__ __forceinline__ float2 upk(u64 v) {
    float2 r; asm("mov.b64 {%0,%1},%2;" : "=f"(r.x), "=f"(r.y) : "l"(v)); return r;
}
__device__ __forceinline__ u64 add2_(u64 a, u64 b) {
    u64 r; asm("add.rn.f32x2 %0,%1,%2;" : "=l"(r) : "l"(a), "l"(b)); return r;
}
__device__ __forceinline__ u64 mul2_(u64 a, u64 b) {
    u64 r; asm("mul.rn.f32x2 %0,%1,%2;" : "=l"(r) : "l"(a), "l"(b)); return r;
}
__device__ __forceinline__ uint32_t spread10(uint32_t x) {
    x &= 0x3FF;
    x = (x | (x << 16)) & 0x030000FF;
    x = (x | (x << 8))  & 0x0300F00F;
    x = (x | (x << 4))  & 0x030C30C3;
    x = (x | (x << 2))  & 0x09249249;
    return x;
}

// ---------------------------------------------------------------- sort (Morton + bitonic)
__global__ void __launch_bounds__(1024, 1)
sort_kernel(const float* __restrict__ xyz) {
    u64* sk = (u64*)s_raw;                         // 16384 keys = 128KB
    __shared__ float sbmin[96], sbmax[96];
    __shared__ float s_mn[3], s_sc[3];

    const int b = blockIdx.x, tid = threadIdx.x;
    const int lane = tid & 31, wid = tid >> 5;
    const float* xb = xyz + (size_t)b * NPTS * 3;

    float mnx = 1e30f, mny = 1e30f, mnz = 1e30f;
    float mxx = -1e30f, mxy = -1e30f, mxz = -1e30f;
    for (int i = tid; i < NPTS; i += 1024) {
        float x = xb[3*i], y = xb[3*i+1], z = xb[3*i+2];
        mnx = fminf(mnx, x); mxx = fmaxf(mxx, x);
        mny = fminf(mny, y); mxy = fmaxf(mxy, y);
        mnz = fminf(mnz, z); mxz = fmaxf(mxz, z);
    }
#pragma unroll
    for (int off = 16; off; off >>= 1) {
        mnx = fminf(mnx, __shfl_xor_sync(~0u, mnx, off));
        mny = fminf(mny, __shfl_xor_sync(~0u, mny, off));
        mnz = fminf(mnz, __shfl_xor_sync(~0u, mnz, off));
        mxx = fmaxf(mxx, __shfl_xor_sync(~0u, mxx, off));
        mxy = fmaxf(mxy, __shfl_xor_sync(~0u, mxy, off));
        mxz = fmaxf(mxz, __shfl_xor_sync(~0u, mxz, off));
    }
    if (lane == 0) {
        sbmin[wid] = mnx; sbmin[32+wid] = mny; sbmin[64+wid] = mnz;
        sbmax[wid] = mxx; sbmax[32+wid] = mxy; sbmax[64+wid] = mxz;
    }
    __syncthreads();
    if (tid < 3) {
        float mn = 1e30f, mx = -1e30f;
        for (int w = 0; w < 32; w++) {
            mn = fminf(mn, sbmin[tid*32 + w]);
            mx = fmaxf(mx, sbmax[tid*32 + w]);
        }
        s_mn[tid] = mn;
        float ext = mx - mn;
        s_sc[tid] = (ext > 0.f) ? 1023.0f / ext : 0.f;
    }
    __syncthreads();
    float bx = s_mn[0], by = s_mn[1], bz = s_mn[2];
    float sx = s_sc[0], sy = s_sc[1], sz = s_sc[2];

    for (int i = tid; i < NPTS; i += 1024) {
        float x = xb[3*i], y = xb[3*i+1], z = xb[3*i+2];
        uint32_t qx = min(1023, max(0, (int)((x - bx) * sx)));
        uint32_t qy = min(1023, max(0, (int)((y - by) * sy)));
        uint32_t qz = min(1023, max(0, (int)((z - bz) * sz)));
        uint32_t code = spread10(qx) | (spread10(qy) << 1) | (spread10(qz) << 2);
        sk[i] = ((u64)code << 14) | (u64)i;
    }
    for (int k = 2; k <= NPTS; k <<= 1)
        for (int j = k >> 1; j > 0; j >>= 1) {
            __syncthreads();
            for (int i = tid; i < NPTS; i += 1024) {
                int ixj = i ^ j;
                if (ixj > i) {
                    bool up = ((i & k) == 0);
                    u64 a = sk[i], c = sk[ixj];
                    if ((a > c) == up) { sk[i] = c; sk[ixj] = a; }
                }
            }
        }
    __syncthreads();
    for (int s = tid; s < NPTS; s += 1024) {
        int p = (int)(sk[s] & 0x3FFF);
        g_sxyz[b*NPTS + s] = make_float4(xb[3*p], xb[3*p+1], xb[3*p+2], __int_as_float(p));
    }
}

// ---------------------------------------------------------------- FPS (chunk-pruned)
__global__ void __launch_bounds__(512, 1)
fps_kernel(const float* __restrict__ xyz, float* __restrict__ out_newxyz) {
    float2* sd2 = (float2*)s_raw;                 // 8192 float2  (64KB)
    int2*   si2 = (int2*)(s_raw + 16384);         // 8192 int2    (64KB)
    __shared__ float s_cx, s_cy, s_cz;
    __shared__ int   s_best[2], s_idx[2];

    const int b = blockIdx.x, tid = threadIdx.x;
    const int lane = tid & 31;
    const float* xb = xyz + (size_t)b * NPTS * 3;

    // load chunk (32 spatially contiguous sorted points) into regs
    u64 px2[16], py2[16], pz2[16];
    float mnx = 1e30f, mny = 1e30f, mnz = 1e30f;
    float mxx = -1e30f, mxy = -1e30f, mxz = -1e30f;
#pragma unroll
    for (int j = 0; j < 16; j++) {
        float4 a = g_sxyz[b*NPTS + tid*CPTS + 2*j];
        float4 c = g_sxyz[b*NPTS + tid*CPTS + 2*j + 1];
        px2[j] = pk(a.x, c.x); py2[j] = pk(a.y, c.y); pz2[j] = pk(a.z, c.z);
        si2[j*512 + tid] = make_int2(__float_as_int(a.w), __float_as_int(c.w));
        sd2[j*512 + tid] = make_float2(1e10f, 1e10f);
        mnx = fminf(mnx, fminf(a.x, c.x)); mxx = fmaxf(mxx, fmaxf(a.x, c.x));
        mny = fminf(mny, fminf(a.y, c.y)); mxy = fmaxf(mxy, fmaxf(a.y, c.y));
        mnz = fminf(mnz, fminf(a.z, c.z)); mxz = fmaxf(mxz, fmaxf(a.z, c.z));
    }
    float ctx = 0.5f * (mnx + mxx), cty = 0.5f * (mny + mxy), ctz = 0.5f * (mnz + mxz);
    float r2 = 0.f;
#pragma unroll
    for (int j = 0; j < 16; j++) {
        float2 fx = upk(px2[j]), fy = upk(py2[j]), fz = upk(pz2[j]);
        float d0 = (fx.x-ctx)*(fx.x-ctx) + (fy.x-cty)*(fy.x-cty) + (fz.x-ctz)*(fz.x-ctz);
        float d1 = (fx.y-ctx)*(fx.y-ctx) + (fy.y-cty)*(fy.y-cty) + (fz.y-ctz)*(fz.y-ctz);
        r2 = fmaxf(r2, fmaxf(d0, d1));
    }
    float cr = sqrtf(r2) * 1.00001f + 1e-12f;
    g_cc[b*NCHUNK + tid] = make_float4(ctx, cty, ctz, cr);

    float chunk_max = 1e10f;
    if (tid == 0) {
        s_cx = xb[0]; s_cy = xb[1]; s_cz = xb[2];
        s_best[0] = 0; s_best[1] = 0;
        s_idx[0] = 0x7fffffff; s_idx[1] = 0x7fffffff;
    }

    for (int t = 0; t < SPTS; t++) {
        const int buf = t & 1;
        __syncthreads();                                  // (A)
        float cx = s_cx, cy = s_cy, cz = s_cz;
        if (tid == 0) {
            out_newxyz[(b*SPTS+t)*3+0] = cx;
            out_newxyz[(b*SPTS+t)*3+1] = cy;
            out_newxyz[(b*SPTS+t)*3+2] = cz;
        }
        // prune test (bounds only; any rounding, conservative margins)
        float ddx = cx - ctx, ddy = cy - cty, ddz = cz - ctz;
        float dc = sqrtf(ddx*ddx + ddy*ddy + ddz*ddz);
        float lb = dc * 0.999999f - cr;
        bool skip = (lb > 0.f) && (lb * lb * 0.999999f >= chunk_max);
        if (!skip) {
            u64 ncx = pk(-cx,-cx), ncy = pk(-cy,-cy), ncz = pk(-cz,-cz);
            float nm = -1.0f;
#pragma unroll
            for (int j = 0; j < 16; j++) {
                u64 dx = add2_(px2[j], ncx);
                u64 dy = add2_(py2[j], ncy);
                u64 dz = add2_(pz2[j], ncz);
                u64 s  = add2_(add2_(mul2_(dx,dx), mul2_(dy,dy)), mul2_(dz,dz));
                float2 sf = upk(s);
                float2 od = sd2[j*512 + tid];
                float n0 = fminf(od.x, sf.x);
                float n1 = fminf(od.y, sf.y);
                if (sf.x < od.x || sf.y < od.y) sd2[j*512 + tid] = make_float2(n0, n1);
                nm = fmaxf(nm, fmaxf(n0, n1));
            }
            chunk_max = nm;
        }
        float v = chunk_max;
#pragma unroll
        for (int off = 16; off; off >>= 1)
            v = fmaxf(v, __shfl_xor_sync(~0u, v, off));
        if (lane == 0) atomicMax(&s_best[buf], __float_as_int(v));
        __syncthreads();                                  // (B)
        float vstar = __int_as_float(s_best[buf]);
        int pmin = 0x7fffffff, jmin = 0, emin = 0;
        if (chunk_max == vstar) {
#pragma unroll
            for (int j = 0; j < 16; j++) {
                float2 od = sd2[j*512 + tid];
                int2   oi = si2[j*512 + tid];
                if (od.x == vstar && oi.x < pmin) { pmin = oi.x; jmin = j; emin = 0; }
                if (od.y == vstar && oi.y < pmin) { pmin = oi.y; jmin = j; emin = 1; }
            }
            atomicMin(&s_idx[buf], pmin);
        }
        __syncthreads();                                  // (C)
        if (pmin != 0x7fffffff && pmin == s_idx[buf]) {
            float vx = 0.f, vy = 0.f, vz = 0.f;
#pragma unroll
            for (int j = 0; j < 16; j++) if (j == jmin) {
                float2 fx = upk(px2[j]), fy = upk(py2[j]), fz = upk(pz2[j]);
                vx = emin ? fx.y : fx.x;
                vy = emin ? fy.y : fy.x;
                vz = emin ? fz.y : fz.x;
            }
            s_cx = vx; s_cy = vy; s_cz = vz;
        }
        if (tid == 0) { s_best[buf^1] = 0; s_idx[buf^1] = 0x7fffffff; }
    }
}

// ---------------------------------------------------------------- 32-NN (chunk-bounded)
__global__ void __launch_bounds__(256)
query_kernel(const float* __restrict__ xyz, const float* __restrict__ newxyz) {
    float* sd    = s_raw;                 // 16384 (fallback) / cd:4096 + ci:4096 (candidate)
    float* cd    = sd;
    int*   ci    = (int*)(sd + 4096);
    float* lbarr = sd + NPTS;             // 512
    float* minv  = lbarr + 512;           // 256
    int*   mino  = (int*)(minv + 256);    // 256
    int*   mins  = mino + 256;            // 256
    int*   clist = mins + 256;            // 128
    __shared__ int s_ub, s_nc;

    const int cid = blockIdx.x, b = cid >> 10, tid = threadIdx.x;
    const float cx = newxyz[cid*3], cy = newxyz[cid*3+1], cz = newxyz[cid*3+2];
    const float cn = sq3(cx, cy, cz);
    const float INF = __int_as_float(0x7f800000);

    if (tid == 0) { s_ub = 0x7f800000; s_nc = 0; }
    __syncthreads();

    for (int c = tid; c < NCHUNK; c += 256) {
        float4 cc = g_cc[b*NCHUNK + c];
        float ddx = cx - cc.x, ddy = cy - cc.y, ddz = cz - cc.z;
        float d = sqrtf(ddx*ddx + ddy*ddy + ddz*ddz);
        float ub = d * 1.000002f + cc.w + 1e-12f;
        float lb = fmaxf(d * 0.999998f - cc.w, 0.f);
        lbarr[c] = lb;
        atomicMin(&s_ub, __float_as_int(ub));
    }
    __syncthreads();
    float ubv = __int_as_float(s_ub);
    for (int c = tid; c < NCHUNK; c += 256) {
        if (lbarr[c] <= ubv) {
            int pos = atomicAdd(&s_nc, 1);
            if (pos < 128) clist[pos] = c;
        }
    }
    __syncthreads();
    int nc = s_nc;
    int* gout = g_group_idx + (size_t)cid * KNN;

    if (nc <= 128) {
        // -------- candidate path
        int np = nc * CPTS;
        int nb = (np + 31) >> 5;
        for (int slot = tid; slot < np; slot += 256) {
            int ch = clist[slot >> 5];
            float4 P = g_sxyz[b*NPTS + ch*CPTS + (slot & 31)];
            float xn = sq3(P.x, P.y, P.z);
            float dot = __fadd_rn(__fadd_rn(__fmul_rn(cx, P.x), __fmul_rn(cy, P.y)),
                                  __fmul_rn(cz, P.z));
            cd[slot] = __fadd_rn(__fadd_rn(cn, __fmul_rn(-2.0f, dot)), xn);
            ci[slot] = __float_as_int(P.w);
        }
        for (int slot = np + tid; slot < nb * 32; slot += 256) {
            cd[slot] = INF; ci[slot] = 0x7fffffff;
        }
        __syncthreads();
        for (int q = tid; q < nb; q += 256) {
            float bv = INF; int bo = 0x7fffffff, bs = q * 32;
            for (int e = 0; e < 32; e++) {
                int slot = q * 32 + e;
                float v = cd[slot]; int o = ci[slot];
                if (v < bv || (v == bv && o < bo)) { bv = v; bo = o; bs = slot; }
            }
            minv[q] = bv; mino[q] = bo; mins[q] = bs;
        }
        __syncthreads();
        if (tid < 32) {
            const int lane = tid;
            for (int sel = 0; sel < KNN; sel++) {
                float bv = INF; int bo = 0x7fffffff, bs = 0;
                for (int q = lane; q < nb; q += 32) {
                    float v = minv[q]; int o = mino[q];
                    if (v < bv || (v == bv && o < bo)) { bv = v; bo = o; bs = mins[q]; }
                }
#pragma unroll
                for (int off = 16; off; off >>= 1) {
                    float ov = __shfl_xor_sync(~0u, bv, off);
                    int   oo = __shfl_xor_sync(~0u, bo, off);
                    int   os = __shfl_xor_sync(~0u, bs, off);
                    if (ov < bv || (ov == bv && oo < bo)) { bv = ov; bo = oo; bs = os; }
                }
                if (lane == 0) { gout[sel] = bo; cd[bs] = INF; }
                __syncwarp();
                int bb = (bs >> 5) & ~0;
                bb = __shfl_sync(~0u, bs, 0) >> 5;
                int slot2 = bb * 32 + lane;
                float nv = cd[slot2]; int no = ci[slot2], ns = slot2;
#pragma unroll
                for (int off = 16; off; off >>= 1) {
                    float ov = __shfl_xor_sync(~0u, nv, off);
                    int   oo = __shfl_xor_sync(~0u, no, off);
                    int   os = __shfl_xor_sync(~0u, ns, off);
                    if (ov < nv || (ov == nv && oo < no)) { nv = ov; no = oo; ns = os; }
                }
                if (lane == 0) { minv[bb] = nv; mino[bb] = no; mins[bb] = ns; }
                __syncwarp();
            }
        }
    } else {
        // -------- fallback: full scan (proven path; xn recomputed, identical bits)
        const float* xb = xyz + (size_t)b * NPTS * 3;
        for (int p = tid; p < NPTS; p += 256) {
            float x = xb[3*p], y = xb[3*p+1], z = xb[3*p+2];
            float xn = sq3(x, y, z);
            float dot = __fadd_rn(__fadd_rn(__fmul_rn(cx, x), __fmul_rn(cy, y)),
                                  __fmul_rn(cz, z));
            sd[p] = __fadd_rn(__fadd_rn(cn, __fmul_rn(-2.0f, dot)), xn);
        }
        __syncthreads();
        {
            float bv = INF; int bi = 0;
            for (int i = 0; i < 64; i++) {
                int idx = tid + (i << 8);
                float v = sd[idx];
                if (v < bv) { bv = v; bi = idx; }
            }
            minv[tid] = bv; mino[tid] = bi;
        }
        __syncthreads();
        if (tid < 32) {
            const int lane = tid;
            for (int sel = 0; sel < KNN; sel++) {
                float bv = INF; int bi = 0x7fffffff;
#pragma unroll
                for (int q = 0; q < 8; q++) {
                    int c = lane + (q << 5);
                    float v = minv[c]; int ii = mino[c];
                    if (v < bv || (v == bv && ii < bi)) { bv = v; bi = ii; }
                }
#pragma unroll
                for (int off = 16; off; off >>= 1) {
                    float ov = __shfl_xor_sync(~0u, bv, off);
                    int   oi = __shfl_xor_sync(~0u, bi, off);
                    if (ov < bv || (ov == bv && oi < bi)) { bv = ov; bi = oi; }
                }
                if (lane == 0) { gout[sel] = bi; sd[bi] = INF; }
                __syncwarp();
                int cs = bi & 255;
                float nv = INF; int ni = 0x7fffffff;
#pragma unroll
                for (int jj = 0; jj < 2; jj++) {
                    int idx = cs + ((2*lane + jj) << 8);
                    float v = sd[idx];
                    if (v < nv || (v == nv && idx < ni)) { nv = v; ni = idx; }
                }
#pragma unroll
                for (int off = 16; off; off >>= 1) {
                    float ov = __shfl_xor_sync(~0u, nv, off);
                    int   oi = __shfl_xor_sync(~0u, ni, off);
                    if (ov < nv || (ov == nv && oi < ni)) { nv = ov; ni = oi; }
                }
                if (lane == 0) { minv[cs] = nv; mino[cs] = ni; }
                __syncwarp();
            }
        }
    }
}

// ---------------------------------------------------------------- MLP (unchanged)
#define FMA4(acc, a, w) \
    acc.x = fmaf(a, w.x, acc.x); acc.y = fmaf(a, w.y, acc.y); \
    acc.z = fmaf(a, w.z, acc.z); acc.w = fmaf(a, w.w, acc.w);

template<int CIN, int COUT, int LDX, int LDY>
__device__ __forceinline__ void layer_mm(const float* X, float* Y, const float* Wk,
                                         const float* sbias, int tid) {
    const int TPC = COUT / 4;
    const float4* W4 = (const float4*)Wk;
    const float4* b4 = (const float4*)sbias;
    for (int tile = tid; tile < 16 * TPC; tile += 256) {
        int r0 = (tile / TPC) * 4, c4 = tile % TPC;
        const float* x0 = X + r0 * LDX;
        const float* x1 = x0 + LDX;
        const float* x2 = x1 + LDX;
        const float* x3 = x2 + LDX;
        float4 acc0 = b4[c4], acc1 = acc0, acc2 = acc0, acc3 = acc0;
#pragma unroll 4
        for (int k4 = 0; k4 < CIN / 4; k4++) {
            float4 xv0 = ((const float4*)x0)[k4];
            float4 xv1 = ((const float4*)x1)[k4];
            float4 xv2 = ((const float4*)x2)[k4];
            float4 xv3 = ((const float4*)x3)[k4];
#pragma unroll
            for (int kk = 0; kk < 4; kk++) {
                float4 w = W4[(k4*4 + kk) * TPC + c4];
                float a0 = (&xv0.x)[kk], a1 = (&xv1.x)[kk];
                float a2 = (&xv2.x)[kk], a3 = (&xv3.x)[kk];
                FMA4(acc0, a0, w) FMA4(acc1, a1, w)
                FMA4(acc2, a2, w) FMA4(acc3, a3, w)
            }
        }
#pragma unroll
        for (int k = (CIN/4)*4; k < CIN; k++) {
            float4 w = W4[k * TPC + c4];
            float a0 = x0[k], a1 = x1[k], a2 = x2[k], a3 = x3[k];
            FMA4(acc0, a0, w) FMA4(acc1, a1, w)
            FMA4(acc2, a2, w) FMA4(acc3, a3, w)
        }
        acc0.x=fmaxf(acc0.x,0.f); acc0.y=fmaxf(acc0.y,0.f); acc0.z=fmaxf(acc0.z,0.f); acc0.w=fmaxf(acc0.w,0.f);
        acc1.x=fmaxf(acc1.x,0.f); acc1.y=fmaxf(acc1.y,0.f); acc1.z=fmaxf(acc1.z,0.f); acc1.w=fmaxf(acc1.w,0.f);
        acc2.x=fmaxf(acc2.x,0.f); acc2.y=fmaxf(acc2.y,0.f); acc2.z=fmaxf(acc2.z,0.f); acc2.w=fmaxf(acc2.w,0.f);
        acc3.x=fmaxf(acc3.x,0.f); acc3.y=fmaxf(acc3.y,0.f); acc3.z=fmaxf(acc3.z,0.f); acc3.w=fmaxf(acc3.w,0.f);
        ((float4*)(Y + (r0  ) * LDY))[c4] = acc0;
        ((float4*)(Y + (r0+1) * LDY))[c4] = acc1;
        ((float4*)(Y + (r0+2) * LDY))[c4] = acc2;
        ((float4*)(Y + (r0+3) * LDY))[c4] = acc3;
    }
}

template<int CIN, int COUT>
__device__ __forceinline__ void fold_bn(const float* w, const float* g, const float* b,
                                        const float* mm, const float* mv,
                                        float* Wk, float* sscale, float* sbias, int tid) {
    if (tid < COUT) {
        float s = g[tid] * rsqrtf(mv[tid] + 1e-3f);
        sscale[tid] = s;
        sbias[tid]  = b[tid] - mm[tid] * s;
    }
    __syncthreads();
    for (int i = tid; i < CIN * COUT; i += 256)
        Wk[i] = w[i] * sscale[i & (COUT - 1)];
    __syncthreads();
}

__global__ void __launch_bounds__(256, 2)
mlp_kernel(const float* __restrict__ xyz, const float* __restrict__ points,
           const float* __restrict__ newxyz,
           const float* __restrict__ w0, const float* __restrict__ g0, const float* __restrict__ b0,
           const float* __restrict__ mm0, const float* __restrict__ mv0,
           const float* __restrict__ w1, const float* __restrict__ g1, const float* __restrict__ b1,
           const float* __restrict__ mm1, const float* __restrict__ mv1,
           const float* __restrict__ w2, const float* __restrict__ g2, const float* __restrict__ b2,
           const float* __restrict__ mm2, const float* __restrict__ mv2,
           float* __restrict__ out_np) {
    float* Xa = s_raw;
    float* Xb = Xa + 64*68;
    float* Wk = Xb + 64*128;
    float* sbias  = Wk + 8192;
    float* sscale = sbias + 128;
    const int tid = threadIdx.x;

    {
        int r = tid >> 2, q = tid & 3;
        int grp = blockIdx.x * 2 + (r >> 5);
        int b = grp >> 10;
        int pidx = g_group_idx[grp * KNN + (r & 31)];
        const float4* p4 = (const float4*)(points + ((size_t)b * NPTS + pidx) * 64);
        float* xr = Xa + r * 68;
#pragma unroll
        for (int m = 0; m < 4; m++) {
            float4 v = p4[q * 4 + m];
            int cc = 3 + (q * 4 + m) * 4;
            xr[cc] = v.x; xr[cc+1] = v.y; xr[cc+2] = v.z; xr[cc+3] = v.w;
        }
        if (q == 0) {
            const float* xp = xyz + ((size_t)b * NPTS + pidx) * 3;
            const float* nx = newxyz + (size_t)grp * 3;
            xr[0] = xp[0] - nx[0]; xr[1] = xp[1] - nx[1]; xr[2] = xp[2] - nx[2];
            xr[67] = 0.f;
        }
    }
    __syncthreads();
    fold_bn<67, 64>(w0, g0, b0, mm0, mv0, Wk, sscale, sbias, tid);
    layer_mm<67, 64, 68, 64>(Xa, Xb, Wk, sbias, tid);
    __syncthreads();
    fold_bn<64, 64>(w1, g1, b1, mm1, mv1, Wk, sscale, sbias, tid);
    layer_mm<64, 64, 64, 68>(Xb, Xa, Wk, sbias, tid);
    __syncthreads();
    fold_bn<64, 128>(w2, g2, b2, mm2, mv2, Wk, sscale, sbias, tid);
    layer_mm<64, 128, 68, 128>(Xa, Xb, Wk, sbias, tid);
    __syncthreads();
    {
        int gl = tid >> 7, c = tid & 127;
        int grp = blockIdx.x * 2 + gl;
        float m = 0.f;
#pragma unroll 8
        for (int nb = 0; nb < 32; nb++)
            m = fmaxf(m, Xb[(gl * 32 + nb) * 128 + c]);
        out_np[(size_t)grp * 128 + c] = m;
    }
}

extern "C" void kernel_launch(void* const* d_in, const int* in_sizes, int n_in,
                              void* d_out, int out_size) {
    const float* xyz    = (const float*)d_in[0];
    const float* points = (const float*)d_in[1];
    const float* w0 = (const float*)d_in[2],  *g0 = (const float*)d_in[3],
               *b0 = (const float*)d_in[4],  *mm0 = (const float*)d_in[5], *mv0 = (const float*)d_in[6];
    const float* w1 = (const float*)d_in[7],  *g1 = (const float*)d_in[8],
               *b1 = (const float*)d_in[9],  *mm1 = (const float*)d_in[10], *mv1 = (const float*)d_in[11];
    const float* w2 = (const float*)d_in[12], *g2 = (const float*)d_in[13],
               *b2 = (const float*)d_in[14], *mm2 = (const float*)d_in[15], *mv2 = (const float*)d_in[16];
    float* out = (float*)d_out;
    float* out_newxyz = out;
    float* out_np     = out + 4*SPTS*3;

    const int SMEM_SORT  = NPTS * 8;                       // 128KB
    const int SMEM_FPS   = NPTS * 8;                       // 128KB (sd2 + si2)
    const int SMEM_QUERY = (NPTS + 512 + 256*3 + 128 + 64) * 4;
    const int SMEM_MLP   = (64*68 + 64*128 + 8192 + 256) * 4;

    cudaFuncSetAttribute(sort_kernel,  cudaFuncAttributeMaxDynamicSharedMemorySize, SMEM_SORT);
    cudaFuncSetAttribute(fps_kernel,   cudaFuncAttributeMaxDynamicSharedMemorySize, SMEM_FPS);
    cudaFuncSetAttribute(query_kernel, cudaFuncAttributeMaxDynamicSharedMemorySize, SMEM_QUERY);
    cudaFuncSetAttribute(mlp_kernel,   cudaFuncAttributeMaxDynamicSharedMemorySize, SMEM_MLP);

    sort_kernel<<<4, 1024, SMEM_SORT>>>(xyz);
    fps_kernel<<<4, 512, SMEM_FPS>>>(xyz, out_newxyz);
    query_kernel<<<4*SPTS, 256, SMEM_QUERY>>>(xyz, out_newxyz);
    mlp_kernel<<<4*SPTS/2, 256, SMEM_MLP>>>(
        xyz, points, out_newxyz,
        w0, g0, b0, mm0, mv0, w1, g1, b1, mm1, mv1, w2, g2, b2, mm2, mv2, out_np);
}

// round 5
// speedup vs baseline: 1.1704x; 1.1704x over previous
#include <cuda_runtime.h>
#include <cstdint>

#define NPTS  16384
#define SPTS  1024
#define KNN   32
#define FPS_CLUSTER 8
#define FPS_THREADS 256
#define PTS_PER_THREAD 8   // 8 CTAs * 256 thr * 8 pts = 16384

typedef unsigned long long u64;

__device__ int   g_group_idx[4*SPTS*KNN];
__device__ float g_xnorm[4*NPTS];

extern __shared__ float s_raw[];

__device__ __forceinline__ float sq3(float x, float y, float z) {
    return __fadd_rn(__fadd_rn(__fmul_rn(x, x), __fmul_rn(y, y)), __fmul_rn(z, z));
}
__device__ __forceinline__ u64 pk(float a, float b) {
    u64 r; asm("mov.b64 %0,{%1,%2};" : "=l"(r) : "f"(a), "f"(b)); return r;
}
__device__ __forceinline__ float2 upk(u64 v) {
    float2 r; asm("mov.b64 {%0,%1},%2;" : "=f"(r.x), "=f"(r.y) : "l"(v)); return r;
}
__device__ __forceinline__ u64 add2_(u64 a, u64 b) {
    u64 r; asm("add.rn.f32x2 %0,%1,%2;" : "=l"(r) : "l"(a), "l"(b)); return r;
}
__device__ __forceinline__ u64 mul2_(u64 a, u64 b) {
    u64 r; asm("mul.rn.f32x2 %0,%1,%2;" : "=l"(r) : "l"(a), "l"(b)); return r;
}
__device__ __forceinline__ uint32_t smem_u32(const void* p) {
    uint32_t a;
    asm("{ .reg .u64 t; cvta.to.shared.u64 t, %1; cvt.u32.u64 %0, t; }" : "=r"(a) : "l"(p));
    return a;
}

// ---------------------------------------------------------------- xnorm
__global__ void xnorm_kernel(const float* __restrict__ xyz) {
    int i = blockIdx.x * blockDim.x + threadIdx.x;
    if (i < 4 * NPTS)
        g_xnorm[i] = sq3(xyz[3*i], xyz[3*i+1], xyz[3*i+2]);
}

// ---------------------------------------------------------------- FPS (8-CTA cluster)
// Per-point running-min lives in registers. Cross-CTA argmax via 64-bit key
// (valbits<<32 | ~idx) exchanged through DSMEM; double-buffered by parity.
__global__ void __launch_bounds__(FPS_THREADS, 1) __cluster_dims__(FPS_CLUSTER, 1, 1)
fps_kernel(const float* __restrict__ xyz, float* __restrict__ out_newxyz) {
    __shared__ u64   s_wkey[8];          // per-warp keys
    __shared__ u64   s_ck[2][FPS_CLUSTER][3]; // [buf][rank] = {key, pk(x,y), pk(z,0)}
    __shared__ float s_cx, s_cy, s_cz;

    const int tid = threadIdx.x, lane = tid & 31, wid = tid >> 5;
    uint32_t rank;
    asm("mov.u32 %0, %%cluster_ctarank;" : "=r"(rank));
    const int b = blockIdx.x >> 3;
    const float* xb = xyz + (size_t)b * NPTS * 3;

    const int base = (int)rank * (NPTS / FPS_CLUSTER) + tid * PTS_PER_THREAD;
    u64 px[4], py[4], pz[4], dd[4];
#pragma unroll
    for (int j = 0; j < 4; j++) {
        int p = base + 2 * j;
        px[j] = pk(xb[3*p],   xb[3*p+3]);
        py[j] = pk(xb[3*p+1], xb[3*p+4]);
        pz[j] = pk(xb[3*p+2], xb[3*p+5]);
        dd[j] = pk(1e10f, 1e10f);
    }
    if (tid == 0) { s_cx = xb[0]; s_cy = xb[1]; s_cz = xb[2]; }

    for (int t = 0; t < SPTS; t++) {
        const int buf = t & 1;
        __syncthreads();                                   // centroid ready
        float cx = s_cx, cy = s_cy, cz = s_cz;
        if (rank == 0 && tid == 0) {
            out_newxyz[(b*SPTS+t)*3+0] = cx;
            out_newxyz[(b*SPTS+t)*3+1] = cy;
            out_newxyz[(b*SPTS+t)*3+2] = cz;
        }
        u64 ncx = pk(-cx,-cx), ncy = pk(-cy,-cy), ncz = pk(-cz,-cz);
        float bv = -1.0f; uint32_t bp = 0;
#pragma unroll
        for (int j = 0; j < 4; j++) {
            u64 dx = add2_(px[j], ncx);
            u64 dy = add2_(py[j], ncy);
            u64 dz = add2_(pz[j], ncz);
            u64 s  = add2_(add2_(mul2_(dx,dx), mul2_(dy,dy)), mul2_(dz,dz));
            float2 sf = upk(s);
            float2 od = upk(dd[j]);
            float n0 = fminf(od.x, sf.x);
            float n1 = fminf(od.y, sf.y);
            dd[j] = pk(n0, n1);
            int p = base + 2 * j;
            if (n0 > bv) { bv = n0; bp = (uint32_t)p; }
            if (n1 > bv) { bv = n1; bp = (uint32_t)(p + 1); }
        }
        u64 key = ((u64)__float_as_uint(bv) << 32) | (u64)(uint32_t)(~bp);
#pragma unroll
        for (int off = 16; off; off >>= 1) {
            u64 o = __shfl_xor_sync(~0u, key, off);
            key = (o > key) ? o : key;
        }
        if (lane == 0) s_wkey[wid] = key;
        __syncthreads();
        if (wid == 0) {
            u64 k = s_wkey[lane & 7];
#pragma unroll
            for (int off = 4; off; off >>= 1) {
                u64 o = __shfl_xor_sync(~0u, k, off);
                k = (o > k) ? o : k;
            }
            if (lane == 0) {
                // prefetch this CTA's candidate coords, ship key+coords to all CTAs
                uint32_t cidx = ~(uint32_t)k;
                float vx = xb[3*cidx], vy = xb[3*cidx+1], vz = xb[3*cidx+2];
                u64 cxy = pk(vx, vy), czz = pk(vz, 0.f);
                uint32_t laddr = smem_u32(&s_ck[buf][rank][0]);
#pragma unroll
                for (int r = 0; r < FPS_CLUSTER; r++) {
                    uint32_t rad;
                    asm("mapa.shared::cluster.u32 %0,%1,%2;" : "=r"(rad) : "r"(laddr), "r"(r));
                    asm volatile("st.shared::cluster.u64 [%0],%1;"     :: "r"(rad),      "l"(k)   : "memory");
                    asm volatile("st.shared::cluster.u64 [%0+8],%1;"   :: "r"(rad),      "l"(cxy) : "memory");
                    asm volatile("st.shared::cluster.u64 [%0+16],%1;"  :: "r"(rad),      "l"(czz) : "memory");
                }
            }
        }
        asm volatile("barrier.cluster.arrive.aligned;" ::: "memory");
        asm volatile("barrier.cluster.wait.aligned;"   ::: "memory");
        if (wid == 0) {
            u64 k = s_ck[buf][lane & 7][0];
#pragma unroll
            for (int off = 4; off; off >>= 1) {
                u64 o = __shfl_xor_sync(~0u, k, off);
                k = (o > k) ? o : k;
            }
            if (lane == 0) {
                uint32_t widx = ~(uint32_t)k;
                int w = widx >> 11;                        // owner rank = idx / 2048
                float2 xy = upk(s_ck[buf][w][1]);
                float2 zz = upk(s_ck[buf][w][2]);
                s_cx = xy.x; s_cy = xy.y; s_cz = zz.x;
            }
        }
    }
}

// ---------------------------------------------------------------- 32-NN (R3 proven)
__global__ void __launch_bounds__(256)
query_kernel(const float* __restrict__ xyz, const float* __restrict__ newxyz) {
    float* sd   = s_raw;            // NPTS
    float* minv = sd + NPTS;        // 256
    int*   mini = (int*)(minv + 256);

    const int cid = blockIdx.x, b = cid >> 10, tid = threadIdx.x;
    const float cx = newxyz[cid*3], cy = newxyz[cid*3+1], cz = newxyz[cid*3+2];
    const float cn = sq3(cx, cy, cz);
    const float* xb  = xyz + (size_t)b * NPTS * 3;
    const float* xnb = g_xnorm + b * NPTS;

    for (int p = tid; p < NPTS; p += 256) {
        float dot = __fadd_rn(__fadd_rn(__fmul_rn(cx, xb[3*p]), __fmul_rn(cy, xb[3*p+1])),
                              __fmul_rn(cz, xb[3*p+2]));
        sd[p] = __fadd_rn(__fadd_rn(cn, __fmul_rn(-2.0f, dot)), xnb[p]);
    }
    __syncthreads();
    {
        float bv = __int_as_float(0x7f800000); int bi = 0;
        for (int i = 0; i < 64; i++) {
            int idx = tid + (i << 8);
            float v = sd[idx];
            if (v < bv) { bv = v; bi = idx; }
        }
        minv[tid] = bv; mini[tid] = bi;
    }
    __syncthreads();
    if (tid < 32) {
        const int lane = tid;
        const float INF = __int_as_float(0x7f800000);
        int* gout = g_group_idx + (size_t)cid * KNN;
        for (int sel = 0; sel < KNN; sel++) {
            float bv = INF; int bi = 0x7fffffff;
#pragma unroll
            for (int q = 0; q < 8; q++) {
                int c = lane + (q << 5);
                float v = minv[c]; int ii = mini[c];
                if (v < bv || (v == bv && ii < bi)) { bv = v; bi = ii; }
            }
#pragma unroll
            for (int off = 16; off; off >>= 1) {
                float ov = __shfl_xor_sync(~0u, bv, off);
                int   oi = __shfl_xor_sync(~0u, bi, off);
                if (ov < bv || (ov == bv && oi < bi)) { bv = ov; bi = oi; }
            }
            if (lane == 0) { gout[sel] = bi; sd[bi] = INF; }
            __syncwarp();
            int cs = bi & 255;
            float nv = INF; int ni = 0x7fffffff;
#pragma unroll
            for (int jj = 0; jj < 2; jj++) {
                int idx = cs + ((2*lane + jj) << 8);
                float v = sd[idx];
                if (v < nv || (v == nv && idx < ni)) { nv = v; ni = idx; }
            }
#pragma unroll
            for (int off = 16; off; off >>= 1) {
                float ov = __shfl_xor_sync(~0u, nv, off);
                int   oi = __shfl_xor_sync(~0u, ni, off);
                if (ov < nv || (ov == nv && oi < ni)) { nv = ov; ni = oi; }
            }
            if (lane == 0) { minv[cs] = nv; mini[cs] = ni; }
            __syncwarp();
        }
    }
}

// ---------------------------------------------------------------- MLP (R3 proven)
#define FMA4(acc, a, w) \
    acc.x = fmaf(a, w.x, acc.x); acc.y = fmaf(a, w.y, acc.y); \
    acc.z = fmaf(a, w.z, acc.z); acc.w = fmaf(a, w.w, acc.w);

template<int CIN, int COUT, int LDX, int LDY>
__device__ __forceinline__ void layer_mm(const float* X, float* Y, const float* Wk,
                                         const float* sbias, int tid) {
    const int TPC = COUT / 4;
    const float4* W4 = (const float4*)Wk;
    const float4* b4 = (const float4*)sbias;
    for (int tile = tid; tile < 16 * TPC; tile += 256) {
        int r0 = (tile / TPC) * 4, c4 = tile % TPC;
        const float* x0 = X + r0 * LDX;
        const float* x1 = x0 + LDX;
        const float* x2 = x1 + LDX;
        const float* x3 = x2 + LDX;
        float4 acc0 = b4[c4], acc1 = acc0, acc2 = acc0, acc3 = acc0;
#pragma unroll 4
        for (int k4 = 0; k4 < CIN / 4; k4++) {
            float4 xv0 = ((const float4*)x0)[k4];
            float4 xv1 = ((const float4*)x1)[k4];
            float4 xv2 = ((const float4*)x2)[k4];
            float4 xv3 = ((const float4*)x3)[k4];
#pragma unroll
            for (int kk = 0; kk < 4; kk++) {
                float4 w = W4[(k4*4 + kk) * TPC + c4];
                float a0 = (&xv0.x)[kk], a1 = (&xv1.x)[kk];
                float a2 = (&xv2.x)[kk], a3 = (&xv3.x)[kk];
                FMA4(acc0, a0, w) FMA4(acc1, a1, w)
                FMA4(acc2, a2, w) FMA4(acc3, a3, w)
            }
        }
#pragma unroll
        for (int k = (CIN/4)*4; k < CIN; k++) {
            float4 w = W4[k * TPC + c4];
            float a0 = x0[k], a1 = x1[k], a2 = x2[k], a3 = x3[k];
            FMA4(acc0, a0, w) FMA4(acc1, a1, w)
            FMA4(acc2, a2, w) FMA4(acc3, a3, w)
        }
        acc0.x=fmaxf(acc0.x,0.f); acc0.y=fmaxf(acc0.y,0.f); acc0.z=fmaxf(acc0.z,0.f); acc0.w=fmaxf(acc0.w,0.f);
        acc1.x=fmaxf(acc1.x,0.f); acc1.y=fmaxf(acc1.y,0.f); acc1.z=fmaxf(acc1.z,0.f); acc1.w=fmaxf(acc1.w,0.f);
        acc2.x=fmaxf(acc2.x,0.f); acc2.y=fmaxf(acc2.y,0.f); acc2.z=fmaxf(acc2.z,0.f); acc2.w=fmaxf(acc2.w,0.f);
        acc3.x=fmaxf(acc3.x,0.f); acc3.y=fmaxf(acc3.y,0.f); acc3.z=fmaxf(acc3.z,0.f); acc3.w=fmaxf(acc3.w,0.f);
        ((float4*)(Y + (r0  ) * LDY))[c4] = acc0;
        ((float4*)(Y + (r0+1) * LDY))[c4] = acc1;
        ((float4*)(Y + (r0+2) * LDY))[c4] = acc2;
        ((float4*)(Y + (r0+3) * LDY))[c4] = acc3;
    }
}

template<int CIN, int COUT>
__device__ __forceinline__ void fold_bn(const float* w, const float* g, const float* b,
                                        const float* mm, const float* mv,
                                        float* Wk, float* sscale, float* sbias, int tid) {
    if (tid < COUT) {
        float s = g[tid] * rsqrtf(mv[tid] + 1e-3f);
        sscale[tid] = s;
        sbias[tid]  = b[tid] - mm[tid] * s;
    }
    __syncthreads();
    for (int i = tid; i < CIN * COUT; i += 256)
        Wk[i] = w[i] * sscale[i & (COUT - 1)];
    __syncthreads();
}

__global__ void __launch_bounds__(256, 2)
mlp_kernel(const float* __restrict__ xyz, const float* __restrict__ points,
           const float* __restrict__ newxyz,
           const float* __restrict__ w0, const float* __restrict__ g0, const float* __restrict__ b0,
           const float* __restrict__ mm0, const float* __restrict__ mv0,
           const float* __restrict__ w1, const float* __restrict__ g1, const float* __restrict__ b1,
           const float* __restrict__ mm1, const float* __restrict__ mv1,
           const float* __restrict__ w2, const float* __restrict__ g2, const float* __restrict__ b2,
           const float* __restrict__ mm2, const float* __restrict__ mv2,
           float* __restrict__ out_np) {
    float* Xa = s_raw;
    float* Xb = Xa + 64*68;
    float* Wk = Xb + 64*128;
    float* sbias  = Wk + 8192;
    float* sscale = sbias + 128;
    const int tid = threadIdx.x;

    {
        int r = tid >> 2, q = tid & 3;
        int grp = blockIdx.x * 2 + (r >> 5);
        int b = grp >> 10;
        int pidx = g_group_idx[grp * KNN + (r & 31)];
        const float4* p4 = (const float4*)(points + ((size_t)b * NPTS + pidx) * 64);
        float* xr = Xa + r * 68;
#pragma unroll
        for (int m = 0; m < 4; m++) {
            float4 v = p4[q * 4 + m];
            int cc = 3 + (q * 4 + m) * 4;
            xr[cc] = v.x; xr[cc+1] = v.y; xr[cc+2] = v.z; xr[cc+3] = v.w;
        }
        if (q == 0) {
            const float* xp = xyz + ((size_t)b * NPTS + pidx) * 3;
            const float* nx = newxyz + (size_t)grp * 3;
            xr[0] = xp[0] - nx[0]; xr[1] = xp[1] - nx[1]; xr[2] = xp[2] - nx[2];
            xr[67] = 0.f;
        }
    }
    __syncthreads();
    fold_bn<67, 64>(w0, g0, b0, mm0, mv0, Wk, sscale, sbias, tid);
    layer_mm<67, 64, 68, 64>(Xa, Xb, Wk, sbias, tid);
    __syncthreads();
    fold_bn<64, 64>(w1, g1, b1, mm1, mv1, Wk, sscale, sbias, tid);
    layer_mm<64, 64, 64, 68>(Xb, Xa, Wk, sbias, tid);
    __syncthreads();
    fold_bn<64, 128>(w2, g2, b2, mm2, mv2, Wk, sscale, sbias, tid);
    layer_mm<64, 128, 68, 128>(Xa, Xb, Wk, sbias, tid);
    __syncthreads();
    {
        int gl = tid >> 7, c = tid & 127;
        int grp = blockIdx.x * 2 + gl;
        float m = 0.f;
#pragma unroll 8
        for (int nb = 0; nb < 32; nb++)
            m = fmaxf(m, Xb[(gl * 32 + nb) * 128 + c]);
        out_np[(size_t)grp * 128 + c] = m;
    }
}

extern "C" void kernel_launch(void* const* d_in, const int* in_sizes, int n_in,
                              void* d_out, int out_size) {
    const float* xyz    = (const float*)d_in[0];
    const float* points = (const float*)d_in[1];
    const float* w0 = (const float*)d_in[2],  *g0 = (const float*)d_in[3],
               *b0 = (const float*)d_in[4],  *mm0 = (const float*)d_in[5], *mv0 = (const float*)d_in[6];
    const float* w1 = (const float*)d_in[7],  *g1 = (const float*)d_in[8],
               *b1 = (const float*)d_in[9],  *mm1 = (const float*)d_in[10], *mv1 = (const float*)d_in[11];
    const float* w2 = (const float*)d_in[12], *g2 = (const float*)d_in[13],
               *b2 = (const float*)d_in[14], *mm2 = (const float*)d_in[15], *mv2 = (const float*)d_in[16];
    float* out = (float*)d_out;
    float* out_newxyz = out;              // [4,1024,3]
    float* out_np     = out + 4*SPTS*3;   // [4,1024,128]

    const int SMEM_QUERY = (NPTS + 256 + 256) * 4;
    const int SMEM_MLP   = (64*68 + 64*128 + 8192 + 256) * 4;

    cudaFuncSetAttribute(query_kernel, cudaFuncAttributeMaxDynamicSharedMemorySize, SMEM_QUERY);
    cudaFuncSetAttribute(mlp_kernel,   cudaFuncAttributeMaxDynamicSharedMemorySize, SMEM_MLP);

    xnorm_kernel<<<(4*NPTS + 255)/256, 256>>>(xyz);
    fps_kernel<<<4 * FPS_CLUSTER, FPS_THREADS>>>(xyz, out_newxyz);
    query_kernel<<<4*SPTS, 256, SMEM_QUERY>>>(xyz, out_newxyz);
    mlp_kernel<<<4*SPTS/2, 256, SMEM_MLP>>>(
        xyz, points, out_newxyz,
        w0, g0, b0, mm0, mv0, w1, g1, b1, mm1, mv1, w2, g2, b2, mm2, mv2, out_np);
}